// round 1
// baseline (speedup 1.0000x reference)
#include <cuda_runtime.h>
#include <cuda_bf16.h>
#include <math.h>

// Shapes (fixed by the problem): B=2, T=512, D=256, H=8, c=32
#define NTOK 1024           // B*T
#define DM   256
#define NH   8
#define HC   32
#define T    512

// Scratch (no cudaMalloc allowed)
__device__ float g_qkv[NTOK * 3 * DM];   // 1024 x 768
__device__ float g_x1 [NTOK * DM];       // 1024 x 256 (x + attn)
__device__ float g_h  [NTOK * 4 * DM];   // 1024 x 1024

// ---------------------------------------------------------------------------
// Generic tiled SGEMM: C[M,N] = act(A[M,K] @ B[K,N] + bias) (+ res)
// BM=BN=64, BK=16, 256 threads, 4x4 micro-tile per thread.
// Requires M%64==0, N%64==0, K%16==0 (true for all three GEMMs here).
// ACT: 0 = none, 1 = quick_gelu. RES: add res[M,N].
// ---------------------------------------------------------------------------
template<int ACT, bool RES>
__global__ void gemm_kernel(const float* __restrict__ A, const float* __restrict__ B,
                            const float* __restrict__ bias, const float* __restrict__ res,
                            float* __restrict__ C, int M, int N, int K)
{
    __shared__ float As[64][17];
    __shared__ float Bs[16][64];

    const int tid = threadIdx.x;
    const int tx = tid & 15;
    const int ty = tid >> 4;
    const int row0 = blockIdx.y * 64;
    const int col0 = blockIdx.x * 64;

    float acc[4][4] = {};

    const int ar = tid >> 2;            // 0..63
    const int ak = (tid & 3) << 2;      // 0,4,8,12
    const int br = tid >> 4;            // 0..15
    const int bc = (tid & 15) << 2;     // 0..60

    for (int k0 = 0; k0 < K; k0 += 16) {
        float4 av = *(const float4*)(A + (size_t)(row0 + ar) * K + k0 + ak);
        As[ar][ak + 0] = av.x; As[ar][ak + 1] = av.y;
        As[ar][ak + 2] = av.z; As[ar][ak + 3] = av.w;

        float4 bv = *(const float4*)(B + (size_t)(k0 + br) * N + col0 + bc);
        *(float4*)&Bs[br][bc] = bv;

        __syncthreads();

        #pragma unroll
        for (int kk = 0; kk < 16; kk++) {
            float a0 = As[ty * 4 + 0][kk];
            float a1 = As[ty * 4 + 1][kk];
            float a2 = As[ty * 4 + 2][kk];
            float a3 = As[ty * 4 + 3][kk];
            float4 b4 = *(float4*)&Bs[kk][tx * 4];
            acc[0][0] += a0 * b4.x; acc[0][1] += a0 * b4.y; acc[0][2] += a0 * b4.z; acc[0][3] += a0 * b4.w;
            acc[1][0] += a1 * b4.x; acc[1][1] += a1 * b4.y; acc[1][2] += a1 * b4.z; acc[1][3] += a1 * b4.w;
            acc[2][0] += a2 * b4.x; acc[2][1] += a2 * b4.y; acc[2][2] += a2 * b4.z; acc[2][3] += a2 * b4.w;
            acc[3][0] += a3 * b4.x; acc[3][1] += a3 * b4.y; acc[3][2] += a3 * b4.z; acc[3][3] += a3 * b4.w;
        }
        __syncthreads();
    }

    #pragma unroll
    for (int i = 0; i < 4; i++) {
        int r = row0 + ty * 4 + i;
        #pragma unroll
        for (int j = 0; j < 4; j++) {
            int c = col0 + tx * 4 + j;
            float v = acc[i][j] + bias[c];
            if (ACT == 1) {
                // quick_gelu: v * sigmoid(1.702 v)
                v = v * __fdividef(1.f, 1.f + __expf(-1.702f * v));
            }
            if (RES) v += res[(size_t)r * N + c];
            C[(size_t)r * N + c] = v;
        }
    }
}

// ---------------------------------------------------------------------------
// L1-distance attention + residual: x1 = x + attn(x)
// Grid: 128 blocks. Block = (b, h, 64-query tile). 256 threads = 8 warps.
// Warp layout: qg = w&1 selects 32-query group, ss = w>>1 selects the 128-key
// split. Each thread: one query, online softmax over 128 keys.
// All lanes of a warp walk the same s -> K/V smem reads are uniform broadcasts.
// smem: K[512][32] + V[512][32] = 128KB; K region reused for the 4-way merge.
// ---------------------------------------------------------------------------
__global__ void attn_kernel(const float* __restrict__ x, const float* __restrict__ qkv,
                            float* __restrict__ x1)
{
    extern __shared__ float sh[];
    float* Ksh = sh;            // 16384 floats
    float* Vsh = sh + 16384;    // 16384 floats

    const int bid = blockIdx.x;         // 0..127
    const int bh  = bid >> 3;           // 0..15
    const int qb  = bid & 7;            // 0..7
    const int b   = bh >> 3;
    const int hh  = bh & 7;
    const int tid = threadIdx.x;
    const int w   = tid >> 5;
    const int lane = tid & 31;
    const int t0  = qb * 64;

    const float* qkv_bh = qkv + (size_t)b * T * 768 + hh * 96;

    // Stage K (cols 32..63) and V (cols 64..95) for this (b,h)
    for (int i = tid; i < T * 8; i += 256) {   // 4096 float4 per matrix
        int s = i >> 3, j = i & 7;
        ((float4*)Ksh)[i] = ((const float4*)(qkv_bh + (size_t)s * 768 + 32))[j];
        ((float4*)Vsh)[i] = ((const float4*)(qkv_bh + (size_t)s * 768 + 64))[j];
    }

    const int qg   = w & 1;
    const int ss   = w >> 1;             // key split 0..3
    const int qidx = qg * 32 + lane;     // 0..63 within tile
    const int t    = t0 + qidx;          // global query token within (b,*)

    float4 q4[8];
    {
        const float4* qsrc = (const float4*)(qkv_bh + (size_t)t * 768);
        #pragma unroll
        for (int j = 0; j < 8; j++) q4[j] = qsrc[j];
    }
    __syncthreads();

    const float scale = 0.1767766952966369f;   // 1/sqrt(32)
    float m = 0.f, l = 0.f;                    // logits are >= 0, so m=0 is a
    float4 o4[8];                              // valid phantom element (p=0)
    #pragma unroll
    for (int j = 0; j < 8; j++) o4[j] = make_float4(0.f, 0.f, 0.f, 0.f);

    const int s_begin = ss * 128;
    for (int s = s_begin; s < s_begin + 128; s++) {
        const float4* krow = (const float4*)(Ksh + s * 32);   // uniform per warp
        float dist = 0.f;
        #pragma unroll
        for (int j = 0; j < 8; j++) {
            float4 kv = krow[j];
            dist += fabsf(q4[j].x - kv.x) + fabsf(q4[j].y - kv.y)
                  + fabsf(q4[j].z - kv.z) + fabsf(q4[j].w - kv.w);
        }
        float wgt = (s == t) ? 0.f : __fdividef(1.f, 0.001f + dist * scale);
        if (wgt > m) {                       // rare after warm-up
            float corr = __expf(m - wgt);
            l *= corr;
            #pragma unroll
            for (int j = 0; j < 8; j++) {
                o4[j].x *= corr; o4[j].y *= corr; o4[j].z *= corr; o4[j].w *= corr;
            }
            m = wgt;
        }
        float p = __expf(wgt - m);
        l += p;
        const float4* vrow = (const float4*)(Vsh + s * 32);   // uniform per warp
        #pragma unroll
        for (int j = 0; j < 8; j++) {
            float4 vv = vrow[j];
            o4[j].x += p * vv.x; o4[j].y += p * vv.y;
            o4[j].z += p * vv.z; o4[j].w += p * vv.w;
        }
    }
    __syncthreads();    // everyone done with K/V smem

    // 4-way split merge (reuse the K region)
    float* mlbuf = Ksh;                 // [64][4][2]
    float* obuf  = Ksh + 512;           // [64][4][32]
    float* Lbuf  = Ksh + 512 + 8192;    // [64]

    mlbuf[(qidx * 4 + ss) * 2 + 0] = m;
    mlbuf[(qidx * 4 + ss) * 2 + 1] = l;
    __syncthreads();

    float M = 0.f;
    #pragma unroll
    for (int i = 0; i < 4; i++) M = fmaxf(M, mlbuf[(qidx * 4 + i) * 2]);
    float L = 0.f;
    #pragma unroll
    for (int i = 0; i < 4; i++)
        L += mlbuf[(qidx * 4 + i) * 2 + 1] * __expf(mlbuf[(qidx * 4 + i) * 2] - M);

    float myscale = __expf(m - M);
    float* od = obuf + (qidx * 4 + ss) * 32;
    #pragma unroll
    for (int j = 0; j < 8; j++) {
        od[j * 4 + 0] = o4[j].x * myscale;
        od[j * 4 + 1] = o4[j].y * myscale;
        od[j * 4 + 2] = o4[j].z * myscale;
        od[j * 4 + 3] = o4[j].w * myscale;
    }
    if (ss == 0) Lbuf[qidx] = L;
    __syncthreads();

    // Final: x1[b, t, hh*32 + c] = x + sum(splits)/L
    for (int e = tid; e < 64 * 32; e += 256) {
        int qi = e >> 5, c = e & 31;
        float sum = obuf[(qi * 4 + 0) * 32 + c] + obuf[(qi * 4 + 1) * 32 + c]
                  + obuf[(qi * 4 + 2) * 32 + c] + obuf[(qi * 4 + 3) * 32 + c];
        float outv = __fdividef(sum, Lbuf[qi]);
        size_t idx = ((size_t)b * T + (t0 + qi)) * DM + hh * HC + c;
        x1[idx] = x[idx] + outv;
    }
}

// ---------------------------------------------------------------------------
extern "C" void kernel_launch(void* const* d_in, const int* in_sizes, int n_in,
                              void* d_out, int out_size)
{
    const float* x      = (const float*)d_in[0];
    const float* W_qkv  = (const float*)d_in[1];
    const float* b_qkv  = (const float*)d_in[2];
    const float* W_fc   = (const float*)d_in[3];
    const float* b_fc   = (const float*)d_in[4];
    const float* W_proj = (const float*)d_in[5];
    const float* b_proj = (const float*)d_in[6];
    float* out = (float*)d_out;

    float *p_qkv, *p_x1, *p_h;
    cudaGetSymbolAddress((void**)&p_qkv, g_qkv);
    cudaGetSymbolAddress((void**)&p_x1,  g_x1);
    cudaGetSymbolAddress((void**)&p_h,   g_h);

    // 1) qkv = x @ W_qkv + b_qkv            (1024 x 768, K=256)
    gemm_kernel<0, false><<<dim3(12, 16), 256>>>(x, W_qkv, b_qkv, nullptr, p_qkv,
                                                 NTOK, 3 * DM, DM);

    // 2) x1 = x + attention(qkv)
    cudaFuncSetAttribute(attn_kernel, cudaFuncAttributeMaxDynamicSharedMemorySize, 131072);
    attn_kernel<<<128, 256, 131072>>>(x, p_qkv, p_x1);

    // 3) h = quick_gelu(x1 @ W_fc + b_fc)   (1024 x 1024, K=256)
    gemm_kernel<1, false><<<dim3(16, 16), 256>>>(p_x1, W_fc, b_fc, nullptr, p_h,
                                                 NTOK, 4 * DM, DM);

    // 4) out = x1 + h @ W_proj + b_proj     (1024 x 256, K=1024)
    gemm_kernel<0, true><<<dim3(4, 16), 256>>>(p_h, W_proj, b_proj, p_x1, out,
                                               NTOK, DM, 4 * DM);
}